// round 10
// baseline (speedup 1.0000x reference)
#include <cuda_runtime.h>
#include <cstdint>

// z: (64,13,128,128) fp32
#define BB 64
#define CC 13
#define HWSZ 16384                       // 128*128
#define NPIX (BB*HWSZ)                   // 1,048,576
#define NTOT (CC*NPIX)                   // 13,631,488

#define THREADS 256
#define TILE 1024                        // pixels per block (one image, contiguous)
#define F_BLOCKS (NPIX / TILE)           // 1024
#define TILES_PER_IMG (HWSZ / TILE)      // 16

// Deterministic scratch (fully overwritten every launch; no runtime allocs).
// Per-block row of 16 floats: [commit, ent, ch0..ch12, pad]
__device__ float g_partials[F_BLOCKS * 16];

__device__ __forceinline__ float warp_sum(float v) {
    #pragma unroll
    for (int o = 16; o; o >>= 1) v += __shfl_xor_sync(0xffffffffu, v, o);
    return v;
}

__device__ __forceinline__ void proc(float zv, float& q, float& commit,
                                     float& ent, float& ca, int& idx) {
    bool pos = zv > 0.0f;
    q = pos ? 1.0f : -1.0f;
    float az = fabsf(zv);
    float d = 1.0f - az;
    commit = fmaf(d, d, commit);
    float a = 4.0f * az;                  // |l0 - l1|
    float e = __expf(-a);                 // in (0,1]
    float r = __fdividef(1.0f, 1.0f + e); // sigmoid(a)
    float ps = e * r;                     // 1 - sigmoid(a)
    ent += fmaf(a, ps, __logf(1.0f + e)); // H(p)
    ca += pos ? r : ps;                   // p0 = sigmoid(4z)
    idx = (idx << 1) | (pos ? 1 : 0);     // MSB = channel 0
}

// ---- Fused kernel: quantize + entropy/commit partials + in-register bitpack ----
__global__ void __launch_bounds__(THREADS)
lfq_fused(const float* __restrict__ z, float* __restrict__ out) {
    int tid = threadIdx.x;
    int blk = blockIdx.x;
    int b    = blk >> 4;                  // image
    int tile = blk & (TILES_PER_IMG - 1);

    // this thread's 4 pixels within its image
    size_t zoff = (size_t)b * (CC * HWSZ) + tile * TILE + tid * 4;

    __shared__ float s_ch[CC][THREADS];   // per-thread per-channel partial (no atomics)
    __shared__ float sw[2][8];

    float commit = 0.0f, ent = 0.0f;
    int i0 = 0, i1 = 0, i2 = 0, i3 = 0;

    float4 nxt = *reinterpret_cast<const float4*>(z + zoff);
    #pragma unroll 1
    for (int c = 0; c < CC; c++) {
        float4 v = nxt;
        if (c + 1 < CC)
            nxt = *reinterpret_cast<const float4*>(z + zoff + (size_t)(c + 1) * HWSZ);
        float4 q;
        float ca = 0.0f;
        proc(v.x, q.x, commit, ent, ca, i0);
        proc(v.y, q.y, commit, ent, ca, i1);
        proc(v.z, q.z, commit, ent, ca, i2);
        proc(v.w, q.w, commit, ent, ca, i3);
        *reinterpret_cast<float4*>(out + zoff + (size_t)c * HWSZ) = q;
        s_ch[c][tid] = ca;                // private slot, conflict-free STS
    }

    // indices straight from registers (8B-aligned region -> float2 stores)
    float* idx_out = out + NTOT + 2;
    int pix = blk * TILE + tid * 4;       // global pixel id
    *reinterpret_cast<float2*>(idx_out + pix)     = make_float2((float)i0, (float)i1);
    *reinterpret_cast<float2*>(idx_out + pix + 2) = make_float2((float)i2, (float)i3);

    // ---- block reductions (deterministic, end-of-block only) ----
    commit = warp_sum(commit);
    ent    = warp_sum(ent);
    int w = tid >> 5, lane = tid & 31;
    if (lane == 0) { sw[0][w] = commit; sw[1][w] = ent; }
    __syncthreads();

    // 8 warps cover 13 channels (w, then w+8 for w<5)
    for (int ch = w; ch < CC; ch += 8) {
        float v = 0.0f;
        #pragma unroll
        for (int k = 0; k < THREADS / 32; k++) v += s_ch[ch][lane + 32 * k];
        v = warp_sum(v);
        if (lane == 0) g_partials[blk * 16 + 2 + ch] = v;
    }
    if (tid == 0) {
        float c0 = 0.0f, e0 = 0.0f;
        #pragma unroll
        for (int i = 0; i < 8; i++) { c0 += sw[0][i]; e0 += sw[1][i]; }
        g_partials[blk * 16 + 0] = c0;
        g_partials[blk * 16 + 1] = e0;
    }
}

// ---- Finalize: one block, all fp32, parallel logs ----
__global__ void __launch_bounds__(512)
lfq_finalize(float* __restrict__ out) {
    int tid = threadIdx.x;
    int w = tid >> 5, lane = tid & 31;
    __shared__ float sch[CC];
    __shared__ float sce[2][16];
    __shared__ float sment;

    float commit = 0.0f, ent = 0.0f;
    for (int r = tid; r < F_BLOCKS; r += 512) {
        commit += g_partials[r * 16 + 0];
        ent    += g_partials[r * 16 + 1];
    }
    commit = warp_sum(commit);
    ent    = warp_sum(ent);
    if (lane == 0) { sce[0][w] = commit; sce[1][w] = ent; }

    // warp w (<13) owns channel w: 1024 rows, 32 per lane
    if (w < CC) {
        float chs = 0.0f;
        for (int r = lane; r < F_BLOCKS; r += 32)
            chs += g_partials[r * 16 + 2 + w];
        chs = warp_sum(chs);
        if (lane == 0) sch[w] = chs;
    }
    __syncthreads();

    if (tid < 32) {
        float me = 0.0f;
        if (tid < CC) {
            float mp = sch[tid] * (1.0f / (float)NPIX);
            mp = fminf(fmaxf(mp, 1e-12f), 1.0f - 1e-7f);
            float mq = 1.0f - mp;
            me = -(mp * __logf(mp) + mq * __logf(mq));
        }
        me = warp_sum(me);
        if (tid == 0) sment = me * (1.0f / (float)CC);
    }
    __syncthreads();

    if (tid == 0) {
        float c0 = 0.0f, e0 = 0.0f;
        #pragma unroll
        for (int i = 0; i < 16; i++) { c0 += sce[0][i]; e0 += sce[1][i]; }
        out[NTOT]     = c0 * (float)(1.25 * 0.1 / (double)NTOT);
        out[NTOT + 1] = (e0 * (float)(1.0 / (double)NTOT) - sment) * 0.1f;
    }
}

extern "C" void kernel_launch(void* const* d_in, const int* in_sizes, int n_in,
                              void* d_out, int out_size) {
    const float* z = (const float*)d_in[0];
    float* out = (float*)d_out;
    lfq_fused<<<F_BLOCKS, THREADS>>>(z, out);
    lfq_finalize<<<1, 512>>>(out);
}